// round 3
// baseline (speedup 1.0000x reference)
#include <cuda_runtime.h>

// ThresholdEncode: out[i][2t]   = (x[i] <= th_t) && (x[i+1] >  th_t)
//                  out[i][2t+1] = (x[i] >  th_t) && (x[i+1] <= th_t)
// th_t = (t+1)/33. Last row zeros. Output [n][64] fp32 = [n][16] float4.
//
// Layout: block = 256 threads = 16 rows x 16 quadrants. Thread's quadrant q
// (and thus both thresholds) is fixed for the whole kernel; only the row
// advances (persistent grid-stride over rows, ILP=4 independent rows/thread).
// Warp writes 512B contiguous per STG.128 group -> perfectly coalesced.

#define ILP 4

__global__ void __launch_bounds__(256) ThresholdEncode_kernel(
    const float* __restrict__ x, float4* __restrict__ out, int n) {

    const int tid = threadIdx.x;
    const int q   = tid & 15;                  // quadrant: fixed per thread
    const float inv33 = 1.0f / 33.0f;
    const float th0 = (float)(2 * q + 1) * inv33;
    const float th1 = (float)(2 * q + 2) * inv33;

    const int rowstride = gridDim.x * 16;      // rows covered per grid step
    const int row0      = blockIdx.x * 16 + (tid >> 4);
    const int nm1       = n - 1;

    for (int row = row0; row < n; row += ILP * rowstride) {
        #pragma unroll
        for (int k = 0; k < ILP; k++) {
            int r = row + k * rowstride;
            if (r < n) {
                float4 v = make_float4(0.f, 0.f, 0.f, 0.f);
                if (r < nm1) {
                    float xp = __ldg(&x[r]);
                    float xn = __ldg(&x[r + 1]);
                    bool a0 = (xp <= th0), b0 = (xn > th0);
                    bool a1 = (xp <= th1), b1 = (xn > th1);
                    v.x = (a0 & b0)    ? 1.0f : 0.0f;   // up(t0)
                    v.y = (!a0 & !b0)  ? 1.0f : 0.0f;   // down(t0)
                    v.z = (a1 & b1)    ? 1.0f : 0.0f;   // up(t1)
                    v.w = (!a1 & !b1)  ? 1.0f : 0.0f;   // down(t1)
                }
                __stcs(&out[r * 16 + q], v);
            }
        }
    }
}

extern "C" void kernel_launch(void* const* d_in, const int* in_sizes, int n_in,
                              void* d_out, int out_size) {
    const float* x = (const float*)d_in[0];
    float4* out = (float4*)d_out;
    int n = in_sizes[0];

    int threads = 256;
    int blocks  = 148 * 8;                     // persistent: 8 CTAs/SM
    int max_blocks = (n + 15) / 16;            // never more blocks than rows
    if (blocks > max_blocks) blocks = max_blocks;
    ThresholdEncode_kernel<<<blocks, threads>>>(x, out, n);
}

// round 4
// speedup vs baseline: 1.0360x; 1.0360x over previous
#include <cuda_runtime.h>

// ThresholdEncode: out[i][2t]   = (x[i] <= th_t) && (x[i+1] >  th_t)
//                  out[i][2t+1] = (x[i] >  th_t) && (x[i+1] <= th_t)
// th_t = (t+1)/33, t in [0,32). Last row zeros. Output [n][64] fp32.
//
// One thread per 32B chunk (8 floats = 4 thresholds) using Blackwell 256-bit
// stores (st.global.v8.f32). Flat grid + ITER independent chunks per thread
// (R2 structure, which benched best). Streaming (.cs) since output is
// write-once.

#define ITER 4

__global__ void __launch_bounds__(256) ThresholdEncode_kernel(
    const float* __restrict__ x, float* __restrict__ out, int n) {

    const int total  = n << 3;                  // n * 8 chunks of 8 floats
    const int stride = gridDim.x * blockDim.x;
    const int i0     = blockIdx.x * blockDim.x + threadIdx.x;
    const float inv33 = 1.0f / 33.0f;
    const int nm1 = n - 1;

    for (int base = i0; base < total; base += ITER * stride) {
        #pragma unroll
        for (int k = 0; k < ITER; k++) {
            int c = base + k * stride;
            if (c < total) {
                int row = c >> 3;
                int oct = c & 7;                // thresholds 4*oct .. 4*oct+3

                float v0 = 0.f, v1 = 0.f, v2 = 0.f, v3 = 0.f;
                float v4 = 0.f, v5 = 0.f, v6 = 0.f, v7 = 0.f;

                if (row < nm1) {
                    float xp = __ldg(&x[row]);
                    float xn = __ldg(&x[row + 1]);

                    float th0 = (float)(4 * oct + 1) * inv33;
                    float th1 = (float)(4 * oct + 2) * inv33;
                    float th2 = (float)(4 * oct + 3) * inv33;
                    float th3 = (float)(4 * oct + 4) * inv33;

                    bool a0 = (xp <= th0), b0 = (xn > th0);
                    bool a1 = (xp <= th1), b1 = (xn > th1);
                    bool a2 = (xp <= th2), b2 = (xn > th2);
                    bool a3 = (xp <= th3), b3 = (xn > th3);

                    v0 = (a0 & b0)   ? 1.0f : 0.0f;
                    v1 = (!a0 & !b0) ? 1.0f : 0.0f;
                    v2 = (a1 & b1)   ? 1.0f : 0.0f;
                    v3 = (!a1 & !b1) ? 1.0f : 0.0f;
                    v4 = (a2 & b2)   ? 1.0f : 0.0f;
                    v5 = (!a2 & !b2) ? 1.0f : 0.0f;
                    v6 = (a3 & b3)   ? 1.0f : 0.0f;
                    v7 = (!a3 & !b3) ? 1.0f : 0.0f;
                }

                // 256-bit streaming store (Blackwell sm_100+)
                asm volatile(
                    "st.global.cs.v8.f32 [%0], {%1,%2,%3,%4,%5,%6,%7,%8};"
                    :: "l"(out + ((long long)c << 3)),
                       "f"(v0), "f"(v1), "f"(v2), "f"(v3),
                       "f"(v4), "f"(v5), "f"(v6), "f"(v7)
                    : "memory");
            }
        }
    }
}

extern "C" void kernel_launch(void* const* d_in, const int* in_sizes, int n_in,
                              void* d_out, int out_size) {
    const float* x = (const float*)d_in[0];
    float* out = (float*)d_out;
    int n = in_sizes[0];

    int total   = n * 8;                        // 32B chunks
    int threads = 256;
    int blocks  = (total + threads * ITER - 1) / (threads * ITER);
    ThresholdEncode_kernel<<<blocks, threads>>>(x, out, n);
}

// round 5
// speedup vs baseline: 1.0468x; 1.0104x over previous
#include <cuda_runtime.h>

// ThresholdEncode: out[i][2t]   = (x[i] <= th_t) && (x[i+1] >  th_t)
//                  out[i][2t+1] = (x[i] >  th_t) && (x[i+1] <= th_t)
// th_t = (t+1)/33, t in [0,32). Last row zeros. Output [n][64] fp32.
//
// One thread per 32B chunk (8 floats = 4 thresholds), Blackwell 256-bit
// streaming stores. Flat grid, ITER=2. Key: stride is a multiple of 8, so a
// thread's octant (c & 7) — and therefore all 4 thresholds — is loop-
// invariant and fully hoisted. We sit at the chip LTS write cap (~6.7 TB/s);
// this round minimizes everything that isn't the store stream.

#define ITER 2

__global__ void __launch_bounds__(256) ThresholdEncode_kernel(
    const float* __restrict__ x, float* __restrict__ out, int n) {

    const int total  = n << 3;                  // n * 8 chunks of 8 floats
    const int stride = gridDim.x * blockDim.x;  // multiple of 8
    const int i0     = blockIdx.x * blockDim.x + threadIdx.x;
    const int nm1    = n - 1;

    // Octant (and thresholds) fixed for this thread across all iterations.
    const int   oct   = i0 & 7;
    const float inv33 = 1.0f / 33.0f;
    const float th0 = (float)(4 * oct + 1) * inv33;
    const float th1 = (float)(4 * oct + 2) * inv33;
    const float th2 = (float)(4 * oct + 3) * inv33;
    const float th3 = (float)(4 * oct + 4) * inv33;

    for (int base = i0; base < total; base += ITER * stride) {
        #pragma unroll
        for (int k = 0; k < ITER; k++) {
            int c = base + k * stride;
            if (c < total) {
                int row = c >> 3;

                float v0 = 0.f, v1 = 0.f, v2 = 0.f, v3 = 0.f;
                float v4 = 0.f, v5 = 0.f, v6 = 0.f, v7 = 0.f;

                if (row < nm1) {
                    float xp = __ldg(&x[row]);
                    float xn = __ldg(&x[row + 1]);

                    bool a0 = (xp <= th0), b0 = (xn > th0);
                    bool a1 = (xp <= th1), b1 = (xn > th1);
                    bool a2 = (xp <= th2), b2 = (xn > th2);
                    bool a3 = (xp <= th3), b3 = (xn > th3);

                    v0 = (a0 & b0)   ? 1.0f : 0.0f;
                    v1 = (!a0 & !b0) ? 1.0f : 0.0f;
                    v2 = (a1 & b1)   ? 1.0f : 0.0f;
                    v3 = (!a1 & !b1) ? 1.0f : 0.0f;
                    v4 = (a2 & b2)   ? 1.0f : 0.0f;
                    v5 = (!a2 & !b2) ? 1.0f : 0.0f;
                    v6 = (a3 & b3)   ? 1.0f : 0.0f;
                    v7 = (!a3 & !b3) ? 1.0f : 0.0f;
                }

                asm volatile(
                    "st.global.cs.v8.f32 [%0], {%1,%2,%3,%4,%5,%6,%7,%8};"
                    :: "l"(out + ((long long)c << 3)),
                       "f"(v0), "f"(v1), "f"(v2), "f"(v3),
                       "f"(v4), "f"(v5), "f"(v6), "f"(v7)
                    : "memory");
            }
        }
    }
}

extern "C" void kernel_launch(void* const* d_in, const int* in_sizes, int n_in,
                              void* d_out, int out_size) {
    const float* x = (const float*)d_in[0];
    float* out = (float*)d_out;
    int n = in_sizes[0];

    int total   = n * 8;                        // 32B chunks
    int threads = 256;
    int blocks  = (total + threads * ITER - 1) / (threads * ITER);
    ThresholdEncode_kernel<<<blocks, threads>>>(x, out, n);
}

// round 6
// speedup vs baseline: 1.1568x; 1.1051x over previous
#include <cuda_runtime.h>

// ThresholdEncode: out[i][2t]   = (x[i] <= th_t) && (x[i+1] >  th_t)
//                  out[i][2t+1] = (x[i] >  th_t) && (x[i+1] <= th_t)
// th_t = (t+1)/33, t in [0,32). Last row zeros. Output [n][64] fp32.
//
// Bench-best structure (R2): one thread per float4 (2 thresholds), flat grid,
// ITER=4 independent STG.128.cs per thread. New: stride is a multiple of 16,
// so the thread's quadrant q = i&15 — and both thresholds — are loop-
// invariant and hoisted; row advances by a constant per iteration.

#define ITER 4

__global__ void __launch_bounds__(256) ThresholdEncode_kernel(
    const float* __restrict__ x, float4* __restrict__ out, int n) {

    const int total  = n << 4;                   // n * 16 float4s
    const int stride = gridDim.x * blockDim.x;   // multiple of 16
    const int i0     = blockIdx.x * blockDim.x + threadIdx.x;
    const int nm1    = n - 1;

    // Quadrant and thresholds: fixed for this thread across all iterations.
    const int   q     = i0 & 15;
    const float inv33 = 1.0f / 33.0f;
    const float th0   = (float)(2 * q + 1) * inv33;
    const float th1   = (float)(2 * q + 2) * inv33;

    const int rowstep = stride >> 4;             // row delta per k-step

    for (int base = i0; base < total; base += ITER * stride) {
        const int row0 = base >> 4;
        #pragma unroll
        for (int k = 0; k < ITER; k++) {
            int c = base + k * stride;
            if (c < total) {
                int row = row0 + k * rowstep;

                float4 v = make_float4(0.f, 0.f, 0.f, 0.f);
                if (row < nm1) {
                    float xp = __ldg(&x[row]);
                    float xn = __ldg(&x[row + 1]);

                    bool a0 = (xp <= th0), b0 = (xn > th0);
                    bool a1 = (xp <= th1), b1 = (xn > th1);

                    v.x = (a0 & b0)   ? 1.0f : 0.0f;   // up(t0)
                    v.y = (!a0 & !b0) ? 1.0f : 0.0f;   // down(t0)
                    v.z = (a1 & b1)   ? 1.0f : 0.0f;   // up(t1)
                    v.w = (!a1 & !b1) ? 1.0f : 0.0f;   // down(t1)
                }
                __stcs(&out[c], v);                    // STG.128, evict-first
            }
        }
    }
}

extern "C" void kernel_launch(void* const* d_in, const int* in_sizes, int n_in,
                              void* d_out, int out_size) {
    const float* x = (const float*)d_in[0];
    float4* out = (float4*)d_out;
    int n = in_sizes[0];

    int total   = n * 16;                        // float4 count
    int threads = 256;
    int blocks  = (total + threads * ITER - 1) / (threads * ITER);
    ThresholdEncode_kernel<<<blocks, threads>>>(x, out, n);
}